// round 1
// baseline (speedup 1.0000x reference)
#include <cuda_runtime.h>
#include <cuda_bf16.h>
#include <math.h>

// Problem constants (shapes are fixed for this problem instance)
#define NN      100000
#define NE      3200000
#define FIN     512
#define HID     64
#define NCLS    47
#define KHOPS   10
#define ALPHA   0.1f
#define ETOT    (NE + NN)   // edges + self loops

// -------- device scratch (no allocations allowed) --------
__device__ int   g_count[NN];        // degree counts (incl. self loop)
__device__ int   g_colptr[NN + 1];   // CSR row pointers (by destination)
__device__ int   g_cursor[NN];       // scatter cursors
__device__ float g_dis[NN];          // D^-1/2
__device__ int   g_incl[NN];         // inclusive per-block scan temp
__device__ int   g_blksum[256];      // block sums for scan
__device__ int2  g_edge[ETOT];       // (src, bitcast weight), sorted by dst
__device__ float g_h0[(size_t)NN * HID];
__device__ float g_hA[(size_t)NN * HID];
__device__ float g_hB[(size_t)NN * HID];

// ---------------- CSR build ----------------
__global__ void k_init_count(int n) {
    int i = blockIdx.x * blockDim.x + threadIdx.x;
    if (i < n) g_count[i] = 1;  // self loop
}

__global__ void k_hist(const int* __restrict__ col, int e) {
    int i = blockIdx.x * blockDim.x + threadIdx.x;
    if (i < e) atomicAdd(&g_count[col[i]], 1);
}

__global__ void k_dis(int n) {
    int i = blockIdx.x * blockDim.x + threadIdx.x;
    if (i < n) g_dis[i] = rsqrtf((float)g_count[i]);
}

// Hillis-Steele block scan (1024/block)
__global__ void k_scan_block(int n) {
    __shared__ int s[1024];
    int i = blockIdx.x * 1024 + threadIdx.x;
    int v = (i < n) ? g_count[i] : 0;
    s[threadIdx.x] = v;
    __syncthreads();
    #pragma unroll
    for (int off = 1; off < 1024; off <<= 1) {
        int t = (threadIdx.x >= off) ? s[threadIdx.x - off] : 0;
        __syncthreads();
        s[threadIdx.x] += t;
        __syncthreads();
    }
    if (i < n) g_incl[i] = s[threadIdx.x];
    if (threadIdx.x == 1023) g_blksum[blockIdx.x] = s[1023];
}

__global__ void k_scan_sums(int nb) {
    if (blockIdx.x == 0 && threadIdx.x == 0) {
        int acc = 0;
        for (int b = 0; b < nb; b++) { int t = g_blksum[b]; g_blksum[b] = acc; acc += t; }
    }
}

__global__ void k_finalize(int n) {
    int i = blockIdx.x * blockDim.x + threadIdx.x;
    if (i == 0) g_colptr[0] = 0;
    if (i < n) {
        int e = g_incl[i] + g_blksum[i >> 10];
        g_colptr[i + 1] = e;
        g_cursor[i] = e - g_count[i];
    }
}

__global__ void k_scatter_edges(const int* __restrict__ row, const int* __restrict__ col, int e) {
    int i = blockIdx.x * blockDim.x + threadIdx.x;
    if (i >= e) return;
    int r = row[i], c = col[i];
    int pos = atomicAdd(&g_cursor[c], 1);
    g_edge[pos] = make_int2(r, __float_as_int(g_dis[r] * g_dis[c]));
}

__global__ void k_scatter_loops(int n) {
    int v = blockIdx.x * blockDim.x + threadIdx.x;
    if (v >= n) return;
    int pos = atomicAdd(&g_cursor[v], 1);
    float d = g_dis[v];
    g_edge[pos] = make_int2(v, __float_as_int(d * d));
}

// ---------------- Embed GEMM: H0 = relu(X @ W + b), [N,512]x[512,64] ----------------
#define BM 64
#define BN 64
#define BK 16
__global__ __launch_bounds__(256) void k_embed(const float* __restrict__ X,
                                               const float* __restrict__ W,
                                               const float* __restrict__ b, int n) {
    __shared__ __align__(16) float Xs[BK][BM];  // k-major, transposed
    __shared__ __align__(16) float Ws[BK][BN];
    int tid = threadIdx.x;
    int tx = tid & 15, ty = tid >> 4;
    int rowBase = blockIdx.x * BM;
    float acc[4][4] = {};

    for (int k0 = 0; k0 < FIN; k0 += BK) {
        {   // X tile: 64 rows x 16 k, float4 per thread
            int r = tid >> 2;
            int kk = (tid & 3) * 4;
            int grow = rowBase + r;
            float4 v = make_float4(0.f, 0.f, 0.f, 0.f);
            if (grow < n) v = *(const float4*)(X + (size_t)grow * FIN + k0 + kk);
            Xs[kk + 0][r] = v.x; Xs[kk + 1][r] = v.y;
            Xs[kk + 2][r] = v.z; Xs[kk + 3][r] = v.w;
        }
        {   // W tile: 16 k x 64 cols
            int k = tid >> 4;
            int c = (tid & 15) * 4;
            *(float4*)&Ws[k][c] = *(const float4*)(W + (size_t)(k0 + k) * HID + c);
        }
        __syncthreads();
        #pragma unroll
        for (int k = 0; k < BK; k++) {
            float4 xv = *(const float4*)&Xs[k][ty * 4];
            float4 wv = *(const float4*)&Ws[k][tx * 4];
            float xr[4] = {xv.x, xv.y, xv.z, xv.w};
            float wc[4] = {wv.x, wv.y, wv.z, wv.w};
            #pragma unroll
            for (int i = 0; i < 4; i++)
                #pragma unroll
                for (int j = 0; j < 4; j++)
                    acc[i][j] += xr[i] * wc[j];
        }
        __syncthreads();
    }
    #pragma unroll
    for (int i = 0; i < 4; i++) {
        int grow = rowBase + ty * 4 + i;
        if (grow >= n) break;
        #pragma unroll
        for (int j = 0; j < 4; j++) {
            int c = tx * 4 + j;
            float v = acc[i][j] + b[c];
            g_h0[(size_t)grow * HID + c] = fmaxf(v, 0.f);
        }
    }
}

// ---------------- Propagation hop: hn[v] = 0.9 * sum_e w*h[src] + 0.1 * h0[v] ----------------
__global__ __launch_bounds__(256) void k_hop(const float* __restrict__ h,
                                             float* __restrict__ hn, int n) {
    int warp = (blockIdx.x * blockDim.x + threadIdx.x) >> 5;
    int lane = threadIdx.x & 31;
    if (warp >= n) return;
    int beg = g_colptr[warp], end = g_colptr[warp + 1];
    float ax = 0.f, ay = 0.f;
    #pragma unroll 4
    for (int e = beg; e < end; e++) {
        int2 ed = __ldg(&g_edge[e]);                       // uniform broadcast
        float w = __int_as_float(ed.y);
        float2 hv = *(const float2*)(h + (size_t)ed.x * HID + lane * 2);
        ax += w * hv.x;
        ay += w * hv.y;
    }
    const float2 h0v = *(const float2*)(g_h0 + (size_t)warp * HID + lane * 2);
    float2 r;
    r.x = (1.f - ALPHA) * ax + ALPHA * h0v.x;
    r.y = (1.f - ALPHA) * ay + ALPHA * h0v.y;
    *(float2*)(hn + (size_t)warp * HID + lane * 2) = r;
}

// ---------------- Predict + softmax family ----------------
__global__ __launch_bounds__(256) void k_pred(const float* __restrict__ h,
                                              const float* __restrict__ Wp,
                                              const float* __restrict__ bp,
                                              float* __restrict__ out,
                                              int n, int out_size) {
    __shared__ float Ws[HID * NCLS];
    __shared__ float bs[NCLS];
    __shared__ float hs[8][HID];
    for (int i = threadIdx.x; i < HID * NCLS; i += blockDim.x) Ws[i] = Wp[i];
    if (threadIdx.x < NCLS) bs[threadIdx.x] = bp[threadIdx.x];
    __syncthreads();

    int warp = threadIdx.x >> 5;
    int lane = threadIdx.x & 31;
    int v = blockIdx.x * 8 + warp;
    if (v >= n) return;

    hs[warp][lane]      = h[(size_t)v * HID + lane];
    hs[warp][lane + 32] = h[(size_t)v * HID + lane + 32];
    __syncwarp();

    int c1 = (lane + 32 < NCLS) ? (lane + 32) : (NCLS - 1);   // lanes >=15 compute a dup, ignored
    float a0 = bs[lane];
    float a1 = bs[c1];
    #pragma unroll
    for (int k = 0; k < HID; k++) {
        float hk = hs[warp][k];
        a0 += hk * Ws[k * NCLS + lane];
        a1 += hk * Ws[k * NCLS + c1];
    }
    bool l1 = (lane + 32 < NCLS);

    // warp-wide max over 47 logits
    float m = fmaxf(a0, l1 ? a1 : -INFINITY);
    #pragma unroll
    for (int o = 16; o > 0; o >>= 1) m = fmaxf(m, __shfl_xor_sync(0xffffffff, m, o));
    float e0 = __expf(a0 - m);
    float e1 = l1 ? __expf(a1 - m) : 0.f;
    float s = e0 + e1;
    #pragma unroll
    for (int o = 16; o > 0; o >>= 1) s += __shfl_xor_sync(0xffffffff, s, o);
    float lse = m + logf(s);
    float inv = 1.f / s;

    size_t base = (size_t)v * NCLS;
    size_t sec  = (size_t)n * NCLS;
    // log_softmax
    out[base + lane] = a0 - lse;
    if (l1) out[base + lane + 32] = a1 - lse;
    // logits
    if (out_size >= 2 * (int)sec) {
        out[sec + base + lane] = a0;
        if (l1) out[sec + base + lane + 32] = a1;
    }
    // softmax
    if (out_size >= 3 * (int)sec) {
        out[2 * sec + base + lane] = e0 * inv;
        if (l1) out[2 * sec + base + lane + 32] = e1 * inv;
    }
}

// ---------------- launch ----------------
extern "C" void kernel_launch(void* const* d_in, const int* in_sizes, int n_in,
                              void* d_out, int out_size) {
    const float* x     = (const float*)d_in[0];   // [N,512]
    const int*   eidx  = (const int*)d_in[1];     // [2,E]
    const float* Wemb  = (const float*)d_in[2];   // [512,64]
    const float* bemb  = (const float*)d_in[3];   // [64]
    const float* Wpred = (const float*)d_in[4];   // [64,47]
    const float* bpred = (const float*)d_in[5];   // [47]
    float* out = (float*)d_out;

    int n = in_sizes[0] / FIN;
    int e = in_sizes[1] / 2;
    const int* row = eidx;       // source
    const int* col = eidx + e;   // target

    int nbN  = (n + 255) / 256;
    int nbE  = (e + 255) / 256;
    int nbS  = (n + 1023) / 1024;

    // --- degree + GCN norm + CSR by destination ---
    k_init_count<<<nbN, 256>>>(n);
    k_hist<<<nbE, 256>>>(col, e);
    k_dis<<<nbN, 256>>>(n);
    k_scan_block<<<nbS, 1024>>>(n);
    k_scan_sums<<<1, 32>>>(nbS);
    k_finalize<<<nbS, 1024>>>(n);
    k_scatter_edges<<<nbE, 256>>>(row, col, e);
    k_scatter_loops<<<nbN, 256>>>(n);

    // --- embed ---
    k_embed<<<(n + BM - 1) / BM, 256>>>(x, Wemb, bemb, n);

    // --- 10 propagation hops (ping-pong, start from h0) ---
    int hopBlocks = (n * 32 + 255) / 256;
    float* cur = nullptr;
    {
        float* h0p; cudaGetSymbolAddress((void**)&h0p, g_h0);
        float* hAp; cudaGetSymbolAddress((void**)&hAp, g_hA);
        float* hBp; cudaGetSymbolAddress((void**)&hBp, g_hB);
        cur = h0p;
        for (int i = 0; i < KHOPS; i++) {
            float* dst = (i & 1) ? hAp : hBp;
            k_hop<<<hopBlocks, 256>>>(cur, dst, n);
            cur = dst;
        }
    }

    // --- predict + softmax family ---
    k_pred<<<(n + 7) / 8, 256>>>(cur, Wpred, bpred, out, n, out_size);
}

// round 2
// speedup vs baseline: 1.0098x; 1.0098x over previous
#include <cuda_runtime.h>
#include <cuda_bf16.h>
#include <math.h>

// Problem constants (shapes are fixed for this problem instance)
#define NN      100000
#define NE      3200000
#define FIN     512
#define HID     64
#define NCLS    47
#define KHOPS   10
#define ALPHA   0.1f
#define ETOT    (NE + NN)   // edges + self loops

// -------- device scratch (no allocations allowed) --------
__device__ int   g_count[NN];        // degree counts (incl. self loop)
__device__ int   g_colptr[NN + 1];   // CSR row pointers (by destination)
__device__ int   g_cursor[NN];       // scatter cursors
__device__ float g_dis[NN];          // D^-1/2
__device__ int   g_incl[NN];         // inclusive per-block scan temp
__device__ int   g_blksum[256];      // block sums for scan
__device__ int2  g_edge[ETOT];       // (src, bitcast weight), sorted by dst
__device__ float g_h0[(size_t)NN * HID];
__device__ float g_hA[(size_t)NN * HID];
__device__ float g_hB[(size_t)NN * HID];

// ---------------- CSR build ----------------
__global__ void k_init_count(int n) {
    int i = blockIdx.x * blockDim.x + threadIdx.x;
    if (i < n) g_count[i] = 1;  // self loop
}

__global__ void k_hist(const int* __restrict__ col, int e) {
    int i = blockIdx.x * blockDim.x + threadIdx.x;
    if (i < e) atomicAdd(&g_count[col[i]], 1);
}

__global__ void k_dis(int n) {
    int i = blockIdx.x * blockDim.x + threadIdx.x;
    if (i < n) g_dis[i] = rsqrtf((float)g_count[i]);
}

// Hillis-Steele block scan (1024/block)
__global__ void k_scan_block(int n) {
    __shared__ int s[1024];
    int i = blockIdx.x * 1024 + threadIdx.x;
    int v = (i < n) ? g_count[i] : 0;
    s[threadIdx.x] = v;
    __syncthreads();
    #pragma unroll
    for (int off = 1; off < 1024; off <<= 1) {
        int t = (threadIdx.x >= off) ? s[threadIdx.x - off] : 0;
        __syncthreads();
        s[threadIdx.x] += t;
        __syncthreads();
    }
    if (i < n) g_incl[i] = s[threadIdx.x];
    if (threadIdx.x == 1023) g_blksum[blockIdx.x] = s[1023];
}

__global__ void k_scan_sums(int nb) {
    if (blockIdx.x == 0 && threadIdx.x == 0) {
        int acc = 0;
        for (int b = 0; b < nb; b++) { int t = g_blksum[b]; g_blksum[b] = acc; acc += t; }
    }
}

__global__ void k_finalize(int n) {
    int i = blockIdx.x * blockDim.x + threadIdx.x;
    if (i == 0) g_colptr[0] = 0;
    if (i < n) {
        int e = g_incl[i] + g_blksum[i >> 10];
        g_colptr[i + 1] = e;
        g_cursor[i] = e - g_count[i];
    }
}

__global__ void k_scatter_edges(const int* __restrict__ row, const int* __restrict__ col, int e) {
    int i = blockIdx.x * blockDim.x + threadIdx.x;
    if (i >= e) return;
    int r = row[i], c = col[i];
    int pos = atomicAdd(&g_cursor[c], 1);
    g_edge[pos] = make_int2(r, __float_as_int(g_dis[r] * g_dis[c]));
}

__global__ void k_scatter_loops(int n) {
    int v = blockIdx.x * blockDim.x + threadIdx.x;
    if (v >= n) return;
    int pos = atomicAdd(&g_cursor[v], 1);
    float d = g_dis[v];
    g_edge[pos] = make_int2(v, __float_as_int(d * d));
}

// ---------------- Embed GEMM: H0 = relu(X @ W + b), [N,512]x[512,64] ----------------
#define BM 64
#define BN 64
#define BK 16
__global__ __launch_bounds__(256) void k_embed(const float* __restrict__ X,
                                               const float* __restrict__ W,
                                               const float* __restrict__ b, int n) {
    __shared__ __align__(16) float Xs[BK][BM];  // k-major, transposed
    __shared__ __align__(16) float Ws[BK][BN];
    int tid = threadIdx.x;
    int tx = tid & 15, ty = tid >> 4;
    int rowBase = blockIdx.x * BM;
    float acc[4][4] = {};

    for (int k0 = 0; k0 < FIN; k0 += BK) {
        {   // X tile: 64 rows x 16 k, float4 per thread
            int r = tid >> 2;
            int kk = (tid & 3) * 4;
            int grow = rowBase + r;
            float4 v = make_float4(0.f, 0.f, 0.f, 0.f);
            if (grow < n) v = *(const float4*)(X + (size_t)grow * FIN + k0 + kk);
            Xs[kk + 0][r] = v.x; Xs[kk + 1][r] = v.y;
            Xs[kk + 2][r] = v.z; Xs[kk + 3][r] = v.w;
        }
        {   // W tile: 16 k x 64 cols
            int k = tid >> 4;
            int c = (tid & 15) * 4;
            *(float4*)&Ws[k][c] = *(const float4*)(W + (size_t)(k0 + k) * HID + c);
        }
        __syncthreads();
        #pragma unroll
        for (int k = 0; k < BK; k++) {
            float4 xv = *(const float4*)&Xs[k][ty * 4];
            float4 wv = *(const float4*)&Ws[k][tx * 4];
            float xr[4] = {xv.x, xv.y, xv.z, xv.w};
            float wc[4] = {wv.x, wv.y, wv.z, wv.w};
            #pragma unroll
            for (int i = 0; i < 4; i++)
                #pragma unroll
                for (int j = 0; j < 4; j++)
                    acc[i][j] += xr[i] * wc[j];
        }
        __syncthreads();
    }
    #pragma unroll
    for (int i = 0; i < 4; i++) {
        int grow = rowBase + ty * 4 + i;
        if (grow >= n) break;
        #pragma unroll
        for (int j = 0; j < 4; j++) {
            int c = tx * 4 + j;
            float v = acc[i][j] + b[c];
            g_h0[(size_t)grow * HID + c] = fmaxf(v, 0.f);
        }
    }
}

// ---------------- Propagation hop: hn[v] = 0.9 * sum_e w*h[src] + 0.1 * h0[v] ----------------
__global__ __launch_bounds__(256) void k_hop(const float* __restrict__ h,
                                             float* __restrict__ hn, int n) {
    int warp = (blockIdx.x * blockDim.x + threadIdx.x) >> 5;
    int lane = threadIdx.x & 31;
    if (warp >= n) return;
    int beg = g_colptr[warp], end = g_colptr[warp + 1];
    float ax = 0.f, ay = 0.f;
    #pragma unroll 4
    for (int e = beg; e < end; e++) {
        int2 ed = __ldg(&g_edge[e]);                       // uniform broadcast
        float w = __int_as_float(ed.y);
        float2 hv = *(const float2*)(h + (size_t)ed.x * HID + lane * 2);
        ax += w * hv.x;
        ay += w * hv.y;
    }
    const float2 h0v = *(const float2*)(g_h0 + (size_t)warp * HID + lane * 2);
    float2 r;
    r.x = (1.f - ALPHA) * ax + ALPHA * h0v.x;
    r.y = (1.f - ALPHA) * ay + ALPHA * h0v.y;
    *(float2*)(hn + (size_t)warp * HID + lane * 2) = r;
}

// ---------------- Predict + softmax family ----------------
__global__ __launch_bounds__(256) void k_pred(const float* __restrict__ h,
                                              const float* __restrict__ Wp,
                                              const float* __restrict__ bp,
                                              float* __restrict__ out,
                                              int n, int out_size) {
    __shared__ float Ws[HID * NCLS];
    __shared__ float bs[NCLS];
    __shared__ float hs[8][HID];
    for (int i = threadIdx.x; i < HID * NCLS; i += blockDim.x) Ws[i] = Wp[i];
    if (threadIdx.x < NCLS) bs[threadIdx.x] = bp[threadIdx.x];
    __syncthreads();

    int warp = threadIdx.x >> 5;
    int lane = threadIdx.x & 31;
    int v = blockIdx.x * 8 + warp;
    if (v >= n) return;

    hs[warp][lane]      = h[(size_t)v * HID + lane];
    hs[warp][lane + 32] = h[(size_t)v * HID + lane + 32];
    __syncwarp();

    int c1 = (lane + 32 < NCLS) ? (lane + 32) : (NCLS - 1);   // lanes >=15 compute a dup, ignored
    float a0 = bs[lane];
    float a1 = bs[c1];
    #pragma unroll
    for (int k = 0; k < HID; k++) {
        float hk = hs[warp][k];
        a0 += hk * Ws[k * NCLS + lane];
        a1 += hk * Ws[k * NCLS + c1];
    }
    bool l1 = (lane + 32 < NCLS);

    // warp-wide max over 47 logits
    float m = fmaxf(a0, l1 ? a1 : -INFINITY);
    #pragma unroll
    for (int o = 16; o > 0; o >>= 1) m = fmaxf(m, __shfl_xor_sync(0xffffffff, m, o));
    float e0 = __expf(a0 - m);
    float e1 = l1 ? __expf(a1 - m) : 0.f;
    float s = e0 + e1;
    #pragma unroll
    for (int o = 16; o > 0; o >>= 1) s += __shfl_xor_sync(0xffffffff, s, o);
    float lse = m + logf(s);
    float inv = 1.f / s;

    size_t base = (size_t)v * NCLS;
    size_t sec  = (size_t)n * NCLS;
    // log_softmax
    out[base + lane] = a0 - lse;
    if (l1) out[base + lane + 32] = a1 - lse;
    // logits
    if (out_size >= 2 * (int)sec) {
        out[sec + base + lane] = a0;
        if (l1) out[sec + base + lane + 32] = a1;
    }
    // softmax
    if (out_size >= 3 * (int)sec) {
        out[2 * sec + base + lane] = e0 * inv;
        if (l1) out[2 * sec + base + lane + 32] = e1 * inv;
    }
}

// ---------------- launch ----------------
extern "C" void kernel_launch(void* const* d_in, const int* in_sizes, int n_in,
                              void* d_out, int out_size) {
    const float* x     = (const float*)d_in[0];   // [N,512]
    const int*   eidx  = (const int*)d_in[1];     // [2,E]
    const float* Wemb  = (const float*)d_in[2];   // [512,64]
    const float* bemb  = (const float*)d_in[3];   // [64]
    const float* Wpred = (const float*)d_in[4];   // [64,47]
    const float* bpred = (const float*)d_in[5];   // [47]
    float* out = (float*)d_out;

    int n = in_sizes[0] / FIN;
    int e = in_sizes[1] / 2;
    const int* row = eidx;       // source
    const int* col = eidx + e;   // target

    int nbN  = (n + 255) / 256;
    int nbE  = (e + 255) / 256;
    int nbS  = (n + 1023) / 1024;

    // --- degree + GCN norm + CSR by destination ---
    k_init_count<<<nbN, 256>>>(n);
    k_hist<<<nbE, 256>>>(col, e);
    k_dis<<<nbN, 256>>>(n);
    k_scan_block<<<nbS, 1024>>>(n);
    k_scan_sums<<<1, 32>>>(nbS);
    k_finalize<<<nbS, 1024>>>(n);
    k_scatter_edges<<<nbE, 256>>>(row, col, e);
    k_scatter_loops<<<nbN, 256>>>(n);

    // --- embed ---
    k_embed<<<(n + BM - 1) / BM, 256>>>(x, Wemb, bemb, n);

    // --- 10 propagation hops (ping-pong, start from h0) ---
    int hopBlocks = (n * 32 + 255) / 256;
    float* cur = nullptr;
    {
        float* h0p; cudaGetSymbolAddress((void**)&h0p, g_h0);
        float* hAp; cudaGetSymbolAddress((void**)&hAp, g_hA);
        float* hBp; cudaGetSymbolAddress((void**)&hBp, g_hB);
        cur = h0p;
        for (int i = 0; i < KHOPS; i++) {
            float* dst = (i & 1) ? hAp : hBp;
            k_hop<<<hopBlocks, 256>>>(cur, dst, n);
            cur = dst;
        }
    }

    // --- predict + softmax family ---
    k_pred<<<(n + 7) / 8, 256>>>(cur, Wpred, bpred, out, n, out_size);
}

// round 3
// speedup vs baseline: 1.2421x; 1.2300x over previous
#include <cuda_runtime.h>
#include <cuda_bf16.h>
#include <cuda_fp16.h>
#include <math.h>

// Problem constants (shapes are fixed for this problem instance)
#define NN      100000
#define NE      3200000
#define FIN     512
#define HID     64
#define NCLS    47
#define KHOPS   10
#define ALPHA   0.1f

// -------- device scratch (no allocations allowed) --------
__device__ int   g_count[NN];        // in-degree counts (real edges only)
__device__ int   g_colptr[NN + 1];   // CSR row pointers (by destination)
__device__ int   g_cursor[NN];       // scatter cursors
__device__ float g_dis[NN];          // D^-1/2 (deg incl. self loop)
__device__ int   g_incl[NN];         // inclusive per-block scan temp
__device__ int   g_blksum[256];      // block sums for scan
__device__ int   g_edge[NE];         // src index, sorted by dst
__device__ __align__(256) float g_h0[(size_t)NN * HID];   // fp32 anchor
__device__ __align__(256) float g_hF[(size_t)NN * HID];   // final fp32 h
__device__ __align__(256) __half2 g_hsA[(size_t)NN * 32]; // scaled fp16 state
__device__ __align__(256) __half2 g_hsB[(size_t)NN * 32];

// ---------------- CSR build ----------------
__global__ void k_init_count(int n) {
    int i = blockIdx.x * blockDim.x + threadIdx.x;
    if (i < n) g_count[i] = 0;
}

__global__ void k_hist(const int* __restrict__ col, int e) {
    int i = blockIdx.x * blockDim.x + threadIdx.x;
    if (i < e) atomicAdd(&g_count[col[i]], 1);
}

__global__ void k_dis(int n) {
    int i = blockIdx.x * blockDim.x + threadIdx.x;
    if (i < n) g_dis[i] = rsqrtf((float)(g_count[i] + 1));  // +1 self loop
}

// Hillis-Steele block scan (1024/block)
__global__ void k_scan_block(int n) {
    __shared__ int s[1024];
    int i = blockIdx.x * 1024 + threadIdx.x;
    int v = (i < n) ? g_count[i] : 0;
    s[threadIdx.x] = v;
    __syncthreads();
    #pragma unroll
    for (int off = 1; off < 1024; off <<= 1) {
        int t = (threadIdx.x >= off) ? s[threadIdx.x - off] : 0;
        __syncthreads();
        s[threadIdx.x] += t;
        __syncthreads();
    }
    if (i < n) g_incl[i] = s[threadIdx.x];
    if (threadIdx.x == 1023) g_blksum[blockIdx.x] = s[1023];
}

__global__ void k_scan_sums(int nb) {
    if (blockIdx.x == 0 && threadIdx.x == 0) {
        int acc = 0;
        for (int b = 0; b < nb; b++) { int t = g_blksum[b]; g_blksum[b] = acc; acc += t; }
    }
}

__global__ void k_finalize(int n) {
    int i = blockIdx.x * blockDim.x + threadIdx.x;
    if (i == 0) g_colptr[0] = 0;
    if (i < n) {
        int e = g_incl[i] + g_blksum[i >> 10];
        g_colptr[i + 1] = e;
        g_cursor[i] = e - g_count[i];
    }
}

__global__ void k_scatter_edges(const int* __restrict__ row, const int* __restrict__ col, int e) {
    int i = blockIdx.x * blockDim.x + threadIdx.x;
    if (i >= e) return;
    int c = col[i];
    int pos = atomicAdd(&g_cursor[c], 1);
    g_edge[pos] = row[i];
}

// ---------------- Embed GEMM: H0 = relu(X @ W + b), [N,512]x[512,64] ----------------
// 128x64 tile, BK=16, 256 threads, 8x4 accumulator per thread.
#define BM 128
#define BN 64
#define BK 16
__global__ __launch_bounds__(256) void k_embed(const float* __restrict__ X,
                                               const float* __restrict__ W,
                                               const float* __restrict__ b, int n) {
    __shared__ __align__(16) float Xs[BK][BM];  // k-major (transposed)
    __shared__ __align__(16) float Ws[BK][BN];
    int tid = threadIdx.x;
    int tx = tid & 15;        // 16 col groups * 4 cols
    int ty = tid >> 4;        // 16 row groups * 8 rows
    int rowBase = blockIdx.x * BM;
    float acc[8][4] = {};

    for (int k0 = 0; k0 < FIN; k0 += BK) {
        {   // X tile: 128 rows x 16 k; 2 float4 per thread
            int r = tid >> 1;
            int kk = (tid & 1) * 8;
            int grow = rowBase + r;
            float4 v0 = make_float4(0.f, 0.f, 0.f, 0.f), v1 = v0;
            if (grow < n) {
                const float* p = X + (size_t)grow * FIN + k0 + kk;
                v0 = *(const float4*)(p);
                v1 = *(const float4*)(p + 4);
            }
            Xs[kk + 0][r] = v0.x; Xs[kk + 1][r] = v0.y;
            Xs[kk + 2][r] = v0.z; Xs[kk + 3][r] = v0.w;
            Xs[kk + 4][r] = v1.x; Xs[kk + 5][r] = v1.y;
            Xs[kk + 6][r] = v1.z; Xs[kk + 7][r] = v1.w;
        }
        {   // W tile: 16 k x 64 cols; 1 float4 per thread
            int k = tid >> 4;
            int c = (tid & 15) * 4;
            *(float4*)&Ws[k][c] = *(const float4*)(W + (size_t)(k0 + k) * HID + c);
        }
        __syncthreads();
        #pragma unroll
        for (int k = 0; k < BK; k++) {
            float4 xa = *(const float4*)&Xs[k][ty * 8];
            float4 xb = *(const float4*)&Xs[k][ty * 8 + 4];
            float4 wv = *(const float4*)&Ws[k][tx * 4];
            float xr[8] = {xa.x, xa.y, xa.z, xa.w, xb.x, xb.y, xb.z, xb.w};
            float wc[4] = {wv.x, wv.y, wv.z, wv.w};
            #pragma unroll
            for (int i = 0; i < 8; i++)
                #pragma unroll
                for (int j = 0; j < 4; j++)
                    acc[i][j] += xr[i] * wc[j];
        }
        __syncthreads();
    }
    #pragma unroll
    for (int i = 0; i < 8; i++) {
        int grow = rowBase + ty * 8 + i;
        if (grow >= n) break;
        float d = g_dis[grow];
        #pragma unroll
        for (int j = 0; j < 4; j += 2) {
            int c = tx * 4 + j;
            float v0 = fmaxf(acc[i][j]     + b[c],     0.f);
            float v1 = fmaxf(acc[i][j + 1] + b[c + 1], 0.f);
            *(float2*)(g_h0 + (size_t)grow * HID + c) = make_float2(v0, v1);
            // initial scaled fp16 state: hs0 = dis * h0
            g_hsA[(size_t)grow * 32 + (c >> 1)] = __floats2half2_rn(d * v0, d * v1);
        }
    }
}

// ---------------- Propagation hop ----------------
// hs = dis (.) h (fp16).  out[v] = 0.9*dis[v]*(sum_{edges} hs[src] + hs[v]) + 0.1*h0[v]
// non-final: write hs_next[v] = dis[v]*out[v] (fp16);  final: write out fp32 to g_hF.
__global__ __launch_bounds__(256) void k_hop(const __half2* __restrict__ hs,
                                             __half2* __restrict__ hn,
                                             int n, int final_hop) {
    int warp = (blockIdx.x * blockDim.x + threadIdx.x) >> 5;
    int lane = threadIdx.x & 31;
    if (warp >= n) return;
    int beg = g_colptr[warp], end = g_colptr[warp + 1];

    // self loop contribution
    float2 self = __half22float2(hs[(size_t)warp * 32 + lane]);
    float ax0 = self.x, ay0 = self.y;
    float ax1 = 0.f, ay1 = 0.f;

    int e = beg;
    for (; e + 1 < end; e += 2) {
        int s0 = __ldg(&g_edge[e]);
        int s1 = __ldg(&g_edge[e + 1]);
        float2 f0 = __half22float2(hs[(size_t)s0 * 32 + lane]);
        float2 f1 = __half22float2(hs[(size_t)s1 * 32 + lane]);
        ax0 += f0.x; ay0 += f0.y;
        ax1 += f1.x; ay1 += f1.y;
    }
    if (e < end) {
        int s0 = __ldg(&g_edge[e]);
        float2 f0 = __half22float2(hs[(size_t)s0 * 32 + lane]);
        ax0 += f0.x; ay0 += f0.y;
    }
    float ax = ax0 + ax1, ay = ay0 + ay1;

    float d = g_dis[warp];
    float2 h0v = *(const float2*)(g_h0 + (size_t)warp * HID + lane * 2);
    float ox = 0.9f * d * ax + 0.1f * h0v.x;
    float oy = 0.9f * d * ay + 0.1f * h0v.y;

    if (final_hop) {
        *(float2*)(g_hF + (size_t)warp * HID + lane * 2) = make_float2(ox, oy);
    } else {
        hn[(size_t)warp * 32 + lane] = __floats2half2_rn(d * ox, d * oy);
    }
}

// ---------------- Predict + softmax family ----------------
__global__ __launch_bounds__(256) void k_pred(const float* __restrict__ h,
                                              const float* __restrict__ Wp,
                                              const float* __restrict__ bp,
                                              float* __restrict__ out,
                                              int n, int out_size) {
    __shared__ float Ws[HID * NCLS];
    __shared__ float bs[NCLS];
    __shared__ float hsm[8][HID];
    for (int i = threadIdx.x; i < HID * NCLS; i += blockDim.x) Ws[i] = Wp[i];
    if (threadIdx.x < NCLS) bs[threadIdx.x] = bp[threadIdx.x];
    __syncthreads();

    int warp = threadIdx.x >> 5;
    int lane = threadIdx.x & 31;
    int v = blockIdx.x * 8 + warp;
    if (v >= n) return;

    hsm[warp][lane]      = h[(size_t)v * HID + lane];
    hsm[warp][lane + 32] = h[(size_t)v * HID + lane + 32];
    __syncwarp();

    int c1 = (lane + 32 < NCLS) ? (lane + 32) : (NCLS - 1);
    float a0 = bs[lane];
    float a1 = bs[c1];
    #pragma unroll
    for (int k = 0; k < HID; k++) {
        float hk = hsm[warp][k];
        a0 += hk * Ws[k * NCLS + lane];
        a1 += hk * Ws[k * NCLS + c1];
    }
    bool l1 = (lane + 32 < NCLS);

    float m = fmaxf(a0, l1 ? a1 : -INFINITY);
    #pragma unroll
    for (int o = 16; o > 0; o >>= 1) m = fmaxf(m, __shfl_xor_sync(0xffffffff, m, o));
    float e0 = __expf(a0 - m);
    float e1 = l1 ? __expf(a1 - m) : 0.f;
    float s = e0 + e1;
    #pragma unroll
    for (int o = 16; o > 0; o >>= 1) s += __shfl_xor_sync(0xffffffff, s, o);
    float lse = m + logf(s);
    float inv = 1.f / s;

    size_t base = (size_t)v * NCLS;
    size_t sec  = (size_t)n * NCLS;
    out[base + lane] = a0 - lse;
    if (l1) out[base + lane + 32] = a1 - lse;
    if (out_size >= 2 * (int)sec) {
        out[sec + base + lane] = a0;
        if (l1) out[sec + base + lane + 32] = a1;
    }
    if (out_size >= 3 * (int)sec) {
        out[2 * sec + base + lane] = e0 * inv;
        if (l1) out[2 * sec + base + lane + 32] = e1 * inv;
    }
}

// ---------------- launch ----------------
extern "C" void kernel_launch(void* const* d_in, const int* in_sizes, int n_in,
                              void* d_out, int out_size) {
    const float* x     = (const float*)d_in[0];   // [N,512]
    const int*   eidx  = (const int*)d_in[1];     // [2,E]
    const float* Wemb  = (const float*)d_in[2];   // [512,64]
    const float* bemb  = (const float*)d_in[3];   // [64]
    const float* Wpred = (const float*)d_in[4];   // [64,47]
    const float* bpred = (const float*)d_in[5];   // [47]
    float* out = (float*)d_out;

    int n = in_sizes[0] / FIN;
    int e = in_sizes[1] / 2;
    const int* row = eidx;       // source
    const int* col = eidx + e;   // target

    int nbN  = (n + 255) / 256;
    int nbE  = (e + 255) / 256;
    int nbS  = (n + 1023) / 1024;

    // --- degree + GCN norm + CSR by destination (real edges only) ---
    k_init_count<<<nbN, 256>>>(n);
    k_hist<<<nbE, 256>>>(col, e);
    k_dis<<<nbN, 256>>>(n);
    k_scan_block<<<nbS, 1024>>>(n);
    k_scan_sums<<<1, 32>>>(nbS);
    k_finalize<<<nbS, 1024>>>(n);
    k_scatter_edges<<<nbE, 256>>>(row, col, e);

    // --- embed (writes fp32 h0 + scaled fp16 hs0) ---
    k_embed<<<(n + BM - 1) / BM, 256>>>(x, Wemb, bemb, n);

    // --- 10 propagation hops (ping-pong fp16 scaled state) ---
    int hopBlocks = (n * 32 + 255) / 256;
    {
        __half2* hAp; cudaGetSymbolAddress((void**)&hAp, g_hsA);
        __half2* hBp; cudaGetSymbolAddress((void**)&hBp, g_hsB);
        __half2* cur = hAp;
        for (int i = 0; i < KHOPS; i++) {
            int fin = (i == KHOPS - 1);
            __half2* dst = (cur == hAp) ? hBp : hAp;
            k_hop<<<hopBlocks, 256>>>(cur, dst, n, fin);
            cur = dst;
        }
    }

    // --- predict + softmax family (reads fp32 g_hF) ---
    float* hFp; cudaGetSymbolAddress((void**)&hFp, g_hF);
    k_pred<<<(n + 7) / 8, 256>>>(hFp, Wpred, bpred, out, n, out_size);
}

// round 4
// speedup vs baseline: 1.3211x; 1.0636x over previous
#include <cuda_runtime.h>
#include <cuda_bf16.h>
#include <cuda_fp16.h>
#include <math.h>

// Problem constants (shapes are fixed for this problem instance)
#define NN      100000
#define NE      3200000
#define FIN     512
#define HID     64
#define NCLS    47
#define KHOPS   10
#define ALPHA   0.1f

// -------- device scratch (no allocations allowed) --------
__device__ int   g_count[NN];        // in-degree counts (real edges only)
__device__ int   g_colptr[NN + 1];   // CSR row pointers (by destination)
__device__ int   g_cursor[NN];       // scatter cursors
__device__ float g_dis[NN];          // D^-1/2 (deg incl. self loop)
__device__ int   g_incl[NN];         // inclusive per-block scan temp
__device__ int   g_blksum[256];      // block sums for scan
__device__ int   g_edge[NE];         // src index, sorted by dst
__device__ __half g_Wt[(size_t)HID * FIN];               // W^T in fp16, [64][512]
__device__ __align__(256) float g_h0[(size_t)NN * HID];   // fp32 anchor
__device__ __align__(256) float g_hF[(size_t)NN * HID];   // final fp32 h
__device__ __align__(256) __half2 g_hsA[(size_t)NN * 32]; // scaled fp16 state
__device__ __align__(256) __half2 g_hsB[(size_t)NN * 32];

// ---------------- CSR build ----------------
__global__ void k_init_count(int n) {
    int i = blockIdx.x * blockDim.x + threadIdx.x;
    if (i < n) g_count[i] = 0;
}

__global__ void k_hist(const int* __restrict__ col, int e) {
    int i = blockIdx.x * blockDim.x + threadIdx.x;
    if (i < e) atomicAdd(&g_count[col[i]], 1);
}

__global__ void k_dis(int n) {
    int i = blockIdx.x * blockDim.x + threadIdx.x;
    if (i < n) g_dis[i] = rsqrtf((float)(g_count[i] + 1));  // +1 self loop
}

// Hillis-Steele block scan (1024/block)
__global__ void k_scan_block(int n) {
    __shared__ int s[1024];
    int i = blockIdx.x * 1024 + threadIdx.x;
    int v = (i < n) ? g_count[i] : 0;
    s[threadIdx.x] = v;
    __syncthreads();
    #pragma unroll
    for (int off = 1; off < 1024; off <<= 1) {
        int t = (threadIdx.x >= off) ? s[threadIdx.x - off] : 0;
        __syncthreads();
        s[threadIdx.x] += t;
        __syncthreads();
    }
    if (i < n) g_incl[i] = s[threadIdx.x];
    if (threadIdx.x == 1023) g_blksum[blockIdx.x] = s[1023];
}

__global__ void k_scan_sums(int nb) {
    if (blockIdx.x == 0 && threadIdx.x == 0) {
        int acc = 0;
        for (int b = 0; b < nb; b++) { int t = g_blksum[b]; g_blksum[b] = acc; acc += t; }
    }
}

__global__ void k_finalize(int n) {
    int i = blockIdx.x * blockDim.x + threadIdx.x;
    if (i == 0) g_colptr[0] = 0;
    if (i < n) {
        int e = g_incl[i] + g_blksum[i >> 10];
        g_colptr[i + 1] = e;
        g_cursor[i] = e - g_count[i];
    }
}

__global__ void k_scatter_edges(const int* __restrict__ row, const int* __restrict__ col, int e) {
    int i = blockIdx.x * blockDim.x + threadIdx.x;
    if (i >= e) return;
    int c = col[i];
    int pos = atomicAdd(&g_cursor[c], 1);
    g_edge[pos] = row[i];
}

// ---------------- W preconvert: g_Wt[n][k] = (half)W[k][n] ----------------
__global__ void k_wconv(const float* __restrict__ W) {
    int i = blockIdx.x * blockDim.x + threadIdx.x;
    if (i < FIN * HID) {
        int k = i >> 6, nn = i & 63;
        g_Wt[(size_t)nn * FIN + k] = __float2half(W[(size_t)k * HID + nn]);
    }
}

// ---------------- Embed GEMM via tensor cores ----------------
// H0 = relu(X @ W + b), fp16 inputs / fp32 accumulate.
// Block: 256 threads (8 warps), tile 128 rows x 64 cols; warp = 16 rows x 64 cols.
#define KC 64
#define XP 8   // halves of padding per smem row
__global__ __launch_bounds__(256) void k_embed_mma(const float* __restrict__ X,
                                                   const float* __restrict__ b, int n) {
    __shared__ __align__(16) __half Xs[128][KC + XP];   // 18.4 KB
    __shared__ __align__(16) __half Ws[64][KC + XP];    // 9.2 KB
    __shared__ float bs[HID];
    int tid = threadIdx.x;
    int wid = tid >> 5, lane = tid & 31;
    int g  = lane >> 2;          // 0..7
    int cq = (lane & 3) * 2;     // 0,2,4,6
    int rowBase = blockIdx.x * 128;
    if (tid < HID) bs[tid] = b[tid];

    float acc[8][4];
    #pragma unroll
    for (int i = 0; i < 8; i++)
        #pragma unroll
        for (int j = 0; j < 4; j++) acc[i][j] = 0.f;

    for (int k0 = 0; k0 < FIN; k0 += KC) {
        {   // X chunk: 128 rows x 64 k; 2 threads/row, 32 floats each, convert to fp16
            int r  = tid >> 1;
            int ks = (tid & 1) * 32;
            int grow = rowBase + r;
            __half2* dst = (__half2*)&Xs[r][ks];
            if (grow < n) {
                const float* p = X + (size_t)grow * FIN + k0 + ks;
                #pragma unroll
                for (int i = 0; i < 8; i++) {
                    float4 v = *(const float4*)(p + i * 4);
                    dst[i * 2 + 0] = __floats2half2_rn(v.x, v.y);
                    dst[i * 2 + 1] = __floats2half2_rn(v.z, v.w);
                }
            } else {
                #pragma unroll
                for (int i = 0; i < 16; i++) dst[i] = __floats2half2_rn(0.f, 0.f);
            }
        }
        {   // W chunk: 64 n x 64 k from preconverted g_Wt
            int nn = tid >> 2;
            int ks = (tid & 3) * 16;
            const uint4* p = (const uint4*)(g_Wt + (size_t)nn * FIN + k0 + ks);
            uint4 v0 = p[0], v1 = p[1];
            *(uint4*)&Ws[nn][ks]     = v0;
            *(uint4*)&Ws[nn][ks + 8] = v1;
        }
        __syncthreads();
        #pragma unroll
        for (int kk = 0; kk < KC; kk += 16) {
            unsigned a0 = *(const unsigned*)&Xs[wid * 16 + g][kk + cq];
            unsigned a1 = *(const unsigned*)&Xs[wid * 16 + g + 8][kk + cq];
            unsigned a2 = *(const unsigned*)&Xs[wid * 16 + g][kk + cq + 8];
            unsigned a3 = *(const unsigned*)&Xs[wid * 16 + g + 8][kk + cq + 8];
            #pragma unroll
            for (int cb = 0; cb < 8; cb++) {
                unsigned b0 = *(const unsigned*)&Ws[cb * 8 + g][kk + cq];
                unsigned b1 = *(const unsigned*)&Ws[cb * 8 + g][kk + cq + 8];
                asm volatile(
                    "mma.sync.aligned.m16n8k16.row.col.f32.f16.f16.f32 "
                    "{%0,%1,%2,%3}, {%4,%5,%6,%7}, {%8,%9}, {%0,%1,%2,%3};"
                    : "+f"(acc[cb][0]), "+f"(acc[cb][1]),
                      "+f"(acc[cb][2]), "+f"(acc[cb][3])
                    : "r"(a0), "r"(a1), "r"(a2), "r"(a3), "r"(b0), "r"(b1));
            }
        }
        __syncthreads();
    }

    // epilogue: bias + relu -> g_h0 (fp32) and dis-scaled fp16 state -> g_hsA
    int r0 = rowBase + wid * 16 + g;
    int r1 = r0 + 8;
    float d0 = (r0 < n) ? g_dis[r0] : 0.f;
    float d1 = (r1 < n) ? g_dis[r1] : 0.f;
    #pragma unroll
    for (int cb = 0; cb < 8; cb++) {
        int c = cb * 8 + cq;
        float bx = bs[c], by = bs[c + 1];
        if (r0 < n) {
            float v0 = fmaxf(acc[cb][0] + bx, 0.f);
            float v1 = fmaxf(acc[cb][1] + by, 0.f);
            *(float2*)(g_h0 + (size_t)r0 * HID + c) = make_float2(v0, v1);
            g_hsA[(size_t)r0 * 32 + (c >> 1)] = __floats2half2_rn(d0 * v0, d0 * v1);
        }
        if (r1 < n) {
            float v0 = fmaxf(acc[cb][2] + bx, 0.f);
            float v1 = fmaxf(acc[cb][3] + by, 0.f);
            *(float2*)(g_h0 + (size_t)r1 * HID + c) = make_float2(v0, v1);
            g_hsA[(size_t)r1 * 32 + (c >> 1)] = __floats2half2_rn(d1 * v0, d1 * v1);
        }
    }
}

// ---------------- Propagation hop ----------------
// hs = dis (.) h (fp16).  out[v] = 0.9*dis[v]*(sum_{edges} hs[src] + hs[v]) + 0.1*h0[v]
__global__ __launch_bounds__(256) void k_hop(const __half2* __restrict__ hs,
                                             __half2* __restrict__ hn,
                                             int n, int final_hop) {
    int warp = (blockIdx.x * blockDim.x + threadIdx.x) >> 5;
    int lane = threadIdx.x & 31;
    if (warp >= n) return;
    int beg = g_colptr[warp], end = g_colptr[warp + 1];

    float2 self = __half22float2(hs[(size_t)warp * 32 + lane]);
    float ax0 = self.x, ay0 = self.y;
    float ax1 = 0.f, ay1 = 0.f;

    int e = beg;
    for (; e + 3 < end; e += 4) {
        int s0 = __ldg(&g_edge[e]);
        int s1 = __ldg(&g_edge[e + 1]);
        int s2 = __ldg(&g_edge[e + 2]);
        int s3 = __ldg(&g_edge[e + 3]);
        float2 f0 = __half22float2(hs[(size_t)s0 * 32 + lane]);
        float2 f1 = __half22float2(hs[(size_t)s1 * 32 + lane]);
        float2 f2 = __half22float2(hs[(size_t)s2 * 32 + lane]);
        float2 f3 = __half22float2(hs[(size_t)s3 * 32 + lane]);
        ax0 += f0.x; ay0 += f0.y;
        ax1 += f1.x; ay1 += f1.y;
        ax0 += f2.x; ay0 += f2.y;
        ax1 += f3.x; ay1 += f3.y;
    }
    for (; e < end; e++) {
        int s0 = __ldg(&g_edge[e]);
        float2 f0 = __half22float2(hs[(size_t)s0 * 32 + lane]);
        ax0 += f0.x; ay0 += f0.y;
    }
    float ax = ax0 + ax1, ay = ay0 + ay1;

    float d = g_dis[warp];
    float2 h0v = *(const float2*)(g_h0 + (size_t)warp * HID + lane * 2);
    float ox = 0.9f * d * ax + 0.1f * h0v.x;
    float oy = 0.9f * d * ay + 0.1f * h0v.y;

    if (final_hop) {
        *(float2*)(g_hF + (size_t)warp * HID + lane * 2) = make_float2(ox, oy);
    } else {
        hn[(size_t)warp * 32 + lane] = __floats2half2_rn(d * ox, d * oy);
    }
}

// ---------------- Predict + softmax family ----------------
__global__ __launch_bounds__(256) void k_pred(const float* __restrict__ h,
                                              const float* __restrict__ Wp,
                                              const float* __restrict__ bp,
                                              float* __restrict__ out,
                                              int n, int out_size) {
    __shared__ float Ws[HID * NCLS];
    __shared__ float bs[NCLS];
    __shared__ float hsm[8][HID];
    for (int i = threadIdx.x; i < HID * NCLS; i += blockDim.x) Ws[i] = Wp[i];
    if (threadIdx.x < NCLS) bs[threadIdx.x] = bp[threadIdx.x];
    __syncthreads();

    int warp = threadIdx.x >> 5;
    int lane = threadIdx.x & 31;
    int v = blockIdx.x * 8 + warp;
    if (v >= n) return;

    hsm[warp][lane]      = h[(size_t)v * HID + lane];
    hsm[warp][lane + 32] = h[(size_t)v * HID + lane + 32];
    __syncwarp();

    int c1 = (lane + 32 < NCLS) ? (lane + 32) : (NCLS - 1);
    float a0 = bs[lane];
    float a1 = bs[c1];
    #pragma unroll
    for (int k = 0; k < HID; k++) {
        float hk = hsm[warp][k];
        a0 += hk * Ws[k * NCLS + lane];
        a1 += hk * Ws[k * NCLS + c1];
    }
    bool l1 = (lane + 32 < NCLS);

    float m = fmaxf(a0, l1 ? a1 : -INFINITY);
    #pragma unroll
    for (int o = 16; o > 0; o >>= 1) m = fmaxf(m, __shfl_xor_sync(0xffffffff, m, o));
    float e0 = __expf(a0 - m);
    float e1 = l1 ? __expf(a1 - m) : 0.f;
    float s = e0 + e1;
    #pragma unroll
    for (int o = 16; o > 0; o >>= 1) s += __shfl_xor_sync(0xffffffff, s, o);
    float lse = m + logf(s);
    float inv = 1.f / s;

    size_t base = (size_t)v * NCLS;
    size_t sec  = (size_t)n * NCLS;
    out[base + lane] = a0 - lse;
    if (l1) out[base + lane + 32] = a1 - lse;
    if (out_size >= 2 * (int)sec) {
        out[sec + base + lane] = a0;
        if (l1) out[sec + base + lane + 32] = a1;
    }
    if (out_size >= 3 * (int)sec) {
        out[2 * sec + base + lane] = e0 * inv;
        if (l1) out[2 * sec + base + lane + 32] = e1 * inv;
    }
}

// ---------------- launch ----------------
extern "C" void kernel_launch(void* const* d_in, const int* in_sizes, int n_in,
                              void* d_out, int out_size) {
    const float* x     = (const float*)d_in[0];   // [N,512]
    const int*   eidx  = (const int*)d_in[1];     // [2,E]
    const float* Wemb  = (const float*)d_in[2];   // [512,64]
    const float* bemb  = (const float*)d_in[3];   // [64]
    const float* Wpred = (const float*)d_in[4];   // [64,47]
    const float* bpred = (const float*)d_in[5];   // [47]
    float* out = (float*)d_out;

    int n = in_sizes[0] / FIN;
    int e = in_sizes[1] / 2;
    const int* row = eidx;       // source
    const int* col = eidx + e;   // target

    int nbN  = (n + 255) / 256;
    int nbE  = (e + 255) / 256;
    int nbS  = (n + 1023) / 1024;

    // --- degree + GCN norm + CSR by destination (real edges only) ---
    k_init_count<<<nbN, 256>>>(n);
    k_hist<<<nbE, 256>>>(col, e);
    k_dis<<<nbN, 256>>>(n);
    k_scan_block<<<nbS, 1024>>>(n);
    k_scan_sums<<<1, 32>>>(nbS);
    k_finalize<<<nbS, 1024>>>(n);
    k_scatter_edges<<<nbE, 256>>>(row, col, e);

    // --- embed: preconvert W to fp16, then tensor-core GEMM ---
    k_wconv<<<(FIN * HID + 255) / 256, 256>>>(Wemb);
    k_embed_mma<<<(n + 127) / 128, 256>>>(x, bemb, n);

    // --- 10 propagation hops (ping-pong fp16 scaled state) ---
    int hopBlocks = (n * 32 + 255) / 256;
    {
        __half2* hAp; cudaGetSymbolAddress((void**)&hAp, g_hsA);
        __half2* hBp; cudaGetSymbolAddress((void**)&hBp, g_hsB);
        __half2* cur = hAp;
        for (int i = 0; i < KHOPS; i++) {
            int fin = (i == KHOPS - 1);
            __half2* dst = (cur == hAp) ? hBp : hAp;
            k_hop<<<hopBlocks, 256>>>(cur, dst, n, fin);
            cur = dst;
        }
    }

    // --- predict + softmax family (reads fp32 g_hF) ---
    float* hFp; cudaGetSymbolAddress((void**)&hFp, g_hF);
    k_pred<<<(n + 7) / 8, 256>>>(hFp, Wpred, bpred, out, n, out_size);
}